// round 1
// baseline (speedup 1.0000x reference)
#include <cuda_runtime.h>
#include <math.h>

// ---------------- problem constants ----------------
#define NL   2
#define Dm   512
#define Nst  16
#define Bb   4
#define Ls   2048
#define Oo   512
#define ML   (Bb*Ls)      // 8192 rows
#define NCH  32           // chunks along L
#define LCH  (Ls/NCH)     // 64

// ---------------- scratch (device globals; no malloc allowed) ----------------
__device__ float g_dt   [ML*Dm];
__device__ float g_bc   [ML*2*Nst];
__device__ float g_y    [ML*Dm];
__device__ float g_mix  [ML*Dm];
__device__ float g_h    [ML*Dm];
__device__ float g_aprod[Bb*NCH*Dm*Nst];
__device__ float g_hend [Bb*NCH*Dm*Nst];
__device__ float g_hstrt[Bb*NCH*Dm*Nst];

// ---------------- helpers ----------------
__device__ __forceinline__ float softplus_f(float v) {
    return fmaxf(v, 0.f) + log1pf(__expf(-fabsf(v)));
}
__device__ __forceinline__ float gelu_f(float v) {
    return 0.5f * v * (1.f + erff(v * 0.70710678118654752f));
}

// ---------------- fp32 SGEMM: C[M,N] = A[M,K] @ W[K,N] + bias (+act) -------
// 128x128 block tile, 8x8 per thread, BK=16, double-buffered smem.
// act: 0 = none, 1 = softplus
__global__ void __launch_bounds__(256, 2) gemm_kernel(
    const float* __restrict__ A, const float* __restrict__ W,
    const float* __restrict__ bias, float* __restrict__ C,
    int N, int K, int act)
{
    __shared__ float As[2][16][136];
    __shared__ float Bs[2][16][128];

    const int tid  = threadIdx.x;
    const int row0 = blockIdx.y * 128;
    const int col0 = blockIdx.x * 128;

    const int am = tid >> 2;          // 0..63 (A tile row, +64 for second)
    const int ak = (tid & 3) << 2;    // 0,4,8,12
    const int bk = tid >> 5;          // 0..7 (B tile k-row, +8 for second)
    const int bn = (tid & 31) << 2;

    const float* Ap = A + (row0 + am) * K + ak;
    const float* Wp = W + bk * N + col0 + bn;

    float acc[8][8];
#pragma unroll
    for (int i = 0; i < 8; ++i)
#pragma unroll
        for (int j = 0; j < 8; ++j) acc[i][j] = 0.f;

    // preload tile 0
    {
        float4 ra0 = *(const float4*)(Ap);
        float4 ra1 = *(const float4*)(Ap + 64 * K);
        float4 rb0 = *(const float4*)(Wp);
        float4 rb1 = *(const float4*)(Wp + 8 * N);
        As[0][ak + 0][am] = ra0.x; As[0][ak + 1][am] = ra0.y;
        As[0][ak + 2][am] = ra0.z; As[0][ak + 3][am] = ra0.w;
        As[0][ak + 0][am + 64] = ra1.x; As[0][ak + 1][am + 64] = ra1.y;
        As[0][ak + 2][am + 64] = ra1.z; As[0][ak + 3][am + 64] = ra1.w;
        *(float4*)&Bs[0][bk][bn]     = rb0;
        *(float4*)&Bs[0][bk + 8][bn] = rb1;
    }
    __syncthreads();

    const int ty = tid >> 4, tx = tid & 15;
    const int m0 = ty << 3, n0 = tx << 3;

    const int ktiles = K >> 4;
    int buf = 0;
    for (int kt = 0; kt < ktiles; ++kt) {
        const bool has = (kt + 1 < ktiles);
        float4 ra0, ra1, rb0, rb1;
        if (has) {
            const float* Ap2 = Ap + ((kt + 1) << 4);
            ra0 = *(const float4*)(Ap2);
            ra1 = *(const float4*)(Ap2 + 64 * K);
            const float* Wp2 = Wp + ((kt + 1) << 4) * N;
            rb0 = *(const float4*)(Wp2);
            rb1 = *(const float4*)(Wp2 + 8 * N);
        }
        {
            const float (*Asb)[136] = As[buf];
            const float (*Bsb)[128] = Bs[buf];
#pragma unroll
            for (int kk = 0; kk < 16; ++kk) {
                float a[8], b[8];
                *(float4*)(a)     = *(const float4*)&Asb[kk][m0];
                *(float4*)(a + 4) = *(const float4*)&Asb[kk][m0 + 4];
                *(float4*)(b)     = *(const float4*)&Bsb[kk][n0];
                *(float4*)(b + 4) = *(const float4*)&Bsb[kk][n0 + 4];
#pragma unroll
                for (int i = 0; i < 8; ++i)
#pragma unroll
                    for (int j = 0; j < 8; ++j)
                        acc[i][j] = fmaf(a[i], b[j], acc[i][j]);
            }
        }
        if (has) {
            buf ^= 1;
            As[buf][ak + 0][am] = ra0.x; As[buf][ak + 1][am] = ra0.y;
            As[buf][ak + 2][am] = ra0.z; As[buf][ak + 3][am] = ra0.w;
            As[buf][ak + 0][am + 64] = ra1.x; As[buf][ak + 1][am + 64] = ra1.y;
            As[buf][ak + 2][am + 64] = ra1.z; As[buf][ak + 3][am + 64] = ra1.w;
            *(float4*)&Bs[buf][bk][bn]     = rb0;
            *(float4*)&Bs[buf][bk + 8][bn] = rb1;
            __syncthreads();
        }
    }

    float bs[8];
#pragma unroll
    for (int j = 0; j < 8; ++j) bs[j] = bias[col0 + n0 + j];
#pragma unroll
    for (int i = 0; i < 8; ++i) {
        float o[8];
#pragma unroll
        for (int j = 0; j < 8; ++j) o[j] = acc[i][j] + bs[j];
        if (act == 1) {
#pragma unroll
            for (int j = 0; j < 8; ++j) o[j] = softplus_f(o[j]);
        }
        float* Cp = C + (row0 + m0 + i) * N + col0 + n0;
        *(float4*)(Cp)     = make_float4(o[0], o[1], o[2], o[3]);
        *(float4*)(Cp + 4) = make_float4(o[4], o[5], o[6], o[7]);
    }
}

// ---------------- B/C projection: out[row][0:16]=x@W_B+b_B, [16:32]=x@W_C+b_C
// block: 32 rows x 32 outputs, 128 threads, K tiled by 64 in smem.
__global__ void __launch_bounds__(128) bc_kernel(
    const float* __restrict__ H, const float* __restrict__ WB,
    const float* __restrict__ bB, const float* __restrict__ WC,
    const float* __restrict__ bC, float* __restrict__ outBC)
{
    __shared__ float sW[64][32];
    __shared__ float sX[32][64];
    const int tid = threadIdx.x;
    const int n = tid & 31;
    const int rbase = (tid >> 5) << 3;     // 0,8,16,24
    const int row0 = blockIdx.x * 32;

    float acc[8];
#pragma unroll
    for (int j = 0; j < 8; ++j) acc[j] = 0.f;

    for (int k0 = 0; k0 < Dm; k0 += 64) {
#pragma unroll
        for (int j = 0; j < 2; ++j) {
            int fid = tid + 128 * j;                 // 0..255
            int kk = fid >> 2, nn = (fid & 3) << 2;
            *(float4*)&sW[kk][nn]      = ((const float4*)(WB + k0 * Nst))[fid];
            *(float4*)&sW[kk][nn + 16] = ((const float4*)(WC + k0 * Nst))[fid];
        }
#pragma unroll
        for (int j = 0; j < 4; ++j) {
            int fid = tid + 128 * j;                 // 0..511
            int r = fid >> 4, cc = (fid & 15) << 2;
            *(float4*)&sX[r][cc] = *(const float4*)(H + (row0 + r) * Dm + k0 + cc);
        }
        __syncthreads();
#pragma unroll
        for (int kk = 0; kk < 64; kk += 4) {
            float w0 = sW[kk][n], w1 = sW[kk + 1][n];
            float w2 = sW[kk + 2][n], w3 = sW[kk + 3][n];
#pragma unroll
            for (int j = 0; j < 8; ++j) {
                float4 xv = *(const float4*)&sX[rbase + j][kk];
                acc[j] = fmaf(xv.x, w0, fmaf(xv.y, w1, fmaf(xv.z, w2, fmaf(xv.w, w3, acc[j]))));
            }
        }
        __syncthreads();
    }
    float bias = (n < 16) ? bB[n] : bC[n & 15];
#pragma unroll
    for (int j = 0; j < 8; ++j)
        outBC[(row0 + rbase + j) * 32 + n] = acc[j] + bias;
}

// ---------------- scan pass 1: per-chunk local scan (zero init) ------------
// thread = (b, chunk c, d); state N=16 in registers. Writes chunk a-prod + h_end.
__global__ void __launch_bounds__(128) scan_pass1(
    const float* __restrict__ dtp, const float* __restrict__ Hp,
    const float* __restrict__ Alog, const float* __restrict__ bc,
    float* __restrict__ apo, float* __restrict__ heo)
{
    __shared__ float sBC[LCH][32];
    const int d = blockIdx.x * 128 + threadIdx.x;
    const int c = blockIdx.y, b = blockIdx.z;
    {
        const float4* src = (const float4*)(bc + (b * Ls + c * LCH) * 32);
        float4* dst = (float4*)sBC;
#pragma unroll
        for (int j = 0; j < 4; ++j) dst[threadIdx.x + 128 * j] = src[threadIdx.x + 128 * j];
    }
    __syncthreads();

    float Ac[16];
    {
        const float4* al = (const float4*)(Alog + d * Nst);
#pragma unroll
        for (int q = 0; q < 4; ++q) {
            float4 v = al[q];
            Ac[4 * q + 0] = -expf(v.x); Ac[4 * q + 1] = -expf(v.y);
            Ac[4 * q + 2] = -expf(v.z); Ac[4 * q + 3] = -expf(v.w);
        }
    }
    float h[16], ap[16];
#pragma unroll
    for (int n = 0; n < 16; ++n) { h[n] = 0.f; ap[n] = 1.f; }

    const float* dtr = dtp + (b * Ls + c * LCH) * Dm + d;
    const float* xr  = Hp  + (b * Ls + c * LCH) * Dm + d;
#pragma unroll 2
    for (int t = 0; t < LCH; ++t) {
        float dt = dtr[t * Dm];
        float xv = xr[t * Dm];
        float dtx = dt * xv;
        float bm[16];
        *(float4*)(bm)      = *(const float4*)&sBC[t][0];
        *(float4*)(bm + 4)  = *(const float4*)&sBC[t][4];
        *(float4*)(bm + 8)  = *(const float4*)&sBC[t][8];
        *(float4*)(bm + 12) = *(const float4*)&sBC[t][12];
#pragma unroll
        for (int n = 0; n < 16; ++n) {
            float a = __expf(dt * Ac[n]);
            ap[n] *= a;
            h[n] = fmaf(a, h[n], dtx * bm[n]);
        }
    }
    const int base = ((b * NCH + c) * Dm + d) * Nst;
    float4* po = (float4*)(apo + base);
    float4* ho = (float4*)(heo + base);
#pragma unroll
    for (int q = 0; q < 4; ++q) {
        po[q] = make_float4(ap[4 * q], ap[4 * q + 1], ap[4 * q + 2], ap[4 * q + 3]);
        ho[q] = make_float4(h[4 * q],  h[4 * q + 1],  h[4 * q + 2],  h[4 * q + 3]);
    }
}

// ---------------- scan pass 2: exclusive scan over chunks ------------------
__global__ void __launch_bounds__(256) scan_pass2(
    const float* __restrict__ ap, const float* __restrict__ he,
    float* __restrict__ hs)
{
    const int g = blockIdx.x * 256 + threadIdx.x;   // < Bb*Dm*Nst = 32768
    const int b = g >> 13;
    const int r = g & 8191;
    float carry = 0.f;
#pragma unroll
    for (int c = 0; c < NCH; ++c) {
        const int off = ((b * NCH + c) << 13) + r;
        hs[off] = carry;
        carry = fmaf(ap[off], carry, he[off]);
    }
}

// ---------------- scan pass 3: re-scan with true init + y + GELU -----------
__global__ void __launch_bounds__(128) scan_pass3(
    const float* __restrict__ dtp, const float* __restrict__ Hp,
    const float* __restrict__ Alog, const float* __restrict__ bc,
    const float* __restrict__ hsi, const float* __restrict__ Dsk,
    float* __restrict__ yout)
{
    __shared__ float sBC[LCH][32];
    const int d = blockIdx.x * 128 + threadIdx.x;
    const int c = blockIdx.y, b = blockIdx.z;
    {
        const float4* src = (const float4*)(bc + (b * Ls + c * LCH) * 32);
        float4* dst = (float4*)sBC;
#pragma unroll
        for (int j = 0; j < 4; ++j) dst[threadIdx.x + 128 * j] = src[threadIdx.x + 128 * j];
    }
    __syncthreads();

    float Ac[16];
    {
        const float4* al = (const float4*)(Alog + d * Nst);
#pragma unroll
        for (int q = 0; q < 4; ++q) {
            float4 v = al[q];
            Ac[4 * q + 0] = -expf(v.x); Ac[4 * q + 1] = -expf(v.y);
            Ac[4 * q + 2] = -expf(v.z); Ac[4 * q + 3] = -expf(v.w);
        }
    }
    float h[16];
    {
        const int base = ((b * NCH + c) * Dm + d) * Nst;
        const float4* hi = (const float4*)(hsi + base);
#pragma unroll
        for (int q = 0; q < 4; ++q) {
            float4 v = hi[q];
            h[4 * q] = v.x; h[4 * q + 1] = v.y; h[4 * q + 2] = v.z; h[4 * q + 3] = v.w;
        }
    }
    const float ds = Dsk[d];
    const float* dtr = dtp + (b * Ls + c * LCH) * Dm + d;
    const float* xr  = Hp  + (b * Ls + c * LCH) * Dm + d;
    float* yr = yout + (b * Ls + c * LCH) * Dm + d;

#pragma unroll 2
    for (int t = 0; t < LCH; ++t) {
        float dt = dtr[t * Dm];
        float xv = xr[t * Dm];
        float dtx = dt * xv;
        float bm[16], cm[16];
        *(float4*)(bm)      = *(const float4*)&sBC[t][0];
        *(float4*)(bm + 4)  = *(const float4*)&sBC[t][4];
        *(float4*)(bm + 8)  = *(const float4*)&sBC[t][8];
        *(float4*)(bm + 12) = *(const float4*)&sBC[t][12];
        *(float4*)(cm)      = *(const float4*)&sBC[t][16];
        *(float4*)(cm + 4)  = *(const float4*)&sBC[t][20];
        *(float4*)(cm + 8)  = *(const float4*)&sBC[t][24];
        *(float4*)(cm + 12) = *(const float4*)&sBC[t][28];
        float y0 = 0.f, y1 = 0.f, y2 = 0.f, y3 = 0.f;
#pragma unroll
        for (int n = 0; n < 16; n += 4) {
            float a0 = __expf(dt * Ac[n + 0]);
            float a1 = __expf(dt * Ac[n + 1]);
            float a2 = __expf(dt * Ac[n + 2]);
            float a3 = __expf(dt * Ac[n + 3]);
            h[n + 0] = fmaf(a0, h[n + 0], dtx * bm[n + 0]);
            h[n + 1] = fmaf(a1, h[n + 1], dtx * bm[n + 1]);
            h[n + 2] = fmaf(a2, h[n + 2], dtx * bm[n + 2]);
            h[n + 3] = fmaf(a3, h[n + 3], dtx * bm[n + 3]);
            y0 = fmaf(cm[n + 0], h[n + 0], y0);
            y1 = fmaf(cm[n + 1], h[n + 1], y1);
            y2 = fmaf(cm[n + 2], h[n + 2], y2);
            y3 = fmaf(cm[n + 3], h[n + 3], y3);
        }
        float y = (y0 + y1) + (y2 + y3);
        y = fmaf(ds, xv, y);
        yr[t * Dm] = gelu_f(y);
    }
}

// ---------------- LayerNorm + residual: Out = H + LN(Y)*g + b --------------
__global__ void __launch_bounds__(128) ln_kernel(
    const float* __restrict__ H, const float* __restrict__ Y,
    const float* __restrict__ g, const float* __restrict__ bt,
    float* __restrict__ Out)
{
    __shared__ float red[8];
    const int row = blockIdx.x, tid = threadIdx.x;
    float4 v = ((const float4*)(Y + row * Dm))[tid];
    float s = v.x + v.y + v.z + v.w;
    float q = v.x * v.x + v.y * v.y + v.z * v.z + v.w * v.w;
#pragma unroll
    for (int o = 16; o; o >>= 1) {
        s += __shfl_xor_sync(0xffffffffu, s, o);
        q += __shfl_xor_sync(0xffffffffu, q, o);
    }
    const int w = tid >> 5;
    if ((tid & 31) == 0) { red[w] = s; red[4 + w] = q; }
    __syncthreads();
    s = red[0] + red[1] + red[2] + red[3];
    q = red[4] + red[5] + red[6] + red[7];
    const float mu = s * (1.f / (float)Dm);
    const float var = q * (1.f / (float)Dm) - mu * mu;
    const float inv = rsqrtf(var + 1e-5f);
    float4 gv = ((const float4*)g)[tid];
    float4 bv = ((const float4*)bt)[tid];
    float4 hv = ((const float4*)(H + row * Dm))[tid];
    float4 o;
    o.x = hv.x + (v.x - mu) * inv * gv.x + bv.x;
    o.y = hv.y + (v.y - mu) * inv * gv.y + bv.y;
    o.z = hv.z + (v.z - mu) * inv * gv.z + bv.z;
    o.w = hv.w + (v.w - mu) * inv * gv.w + bv.w;
    ((float4*)(Out + row * Dm))[tid] = o;
}

// ---------------- host launch ----------------
extern "C" void kernel_launch(void* const* d_in, const int* in_sizes, int n_in,
                              void* d_out, int out_size)
{
    const float* x     = (const float*)d_in[0];
    const float* A_log = (const float*)d_in[1];
    const float* W_B   = (const float*)d_in[2];
    const float* b_B   = (const float*)d_in[3];
    const float* W_C   = (const float*)d_in[4];
    const float* b_C   = (const float*)d_in[5];
    const float* W_dt  = (const float*)d_in[6];
    const float* b_dt  = (const float*)d_in[7];
    const float* Dsk   = (const float*)d_in[8];
    const float* W_mix = (const float*)d_in[9];
    const float* b_mix = (const float*)d_in[10];
    const float* ln_g  = (const float*)d_in[11];
    const float* ln_b  = (const float*)d_in[12];
    const float* W_dec = (const float*)d_in[13];
    const float* b_dec = (const float*)d_in[14];
    float* out = (float*)d_out;

    void* p;
    cudaGetSymbolAddress(&p, g_dt);    float* gdt = (float*)p;
    cudaGetSymbolAddress(&p, g_bc);    float* gbc = (float*)p;
    cudaGetSymbolAddress(&p, g_y);     float* gy  = (float*)p;
    cudaGetSymbolAddress(&p, g_mix);   float* gmx = (float*)p;
    cudaGetSymbolAddress(&p, g_h);     float* gh  = (float*)p;
    cudaGetSymbolAddress(&p, g_aprod); float* gap = (float*)p;
    cudaGetSymbolAddress(&p, g_hend);  float* ghe = (float*)p;
    cudaGetSymbolAddress(&p, g_hstrt); float* ghs = (float*)p;

    const dim3 gemmGrid(Dm / 128, ML / 128);   // (4, 64)
    const dim3 scanGrid(Dm / 128, NCH, Bb);    // (4, 32, 4)

    const float* H = x;
    for (int i = 0; i < NL; ++i) {
        gemm_kernel<<<gemmGrid, 256>>>(H, W_dt + i * Dm * Dm, b_dt + i * Dm,
                                       gdt, Dm, Dm, 1);
        bc_kernel<<<ML / 32, 128>>>(H, W_B + i * Dm * Nst, b_B + i * Nst,
                                    W_C + i * Dm * Nst, b_C + i * Nst, gbc);
        scan_pass1<<<scanGrid, 128>>>(gdt, H, A_log + i * Dm * Nst, gbc, gap, ghe);
        scan_pass2<<<(Bb * Dm * Nst) / 256, 256>>>(gap, ghe, ghs);
        scan_pass3<<<scanGrid, 128>>>(gdt, H, A_log + i * Dm * Nst, gbc, ghs,
                                      Dsk + i * Dm, gy);
        gemm_kernel<<<gemmGrid, 256>>>(gy, W_mix + i * Dm * Dm, b_mix + i * Dm,
                                       gmx, Dm, Dm, 0);
        ln_kernel<<<ML, 128>>>(H, gmx, ln_g + i * Dm, ln_b + i * Dm, gh);
        H = gh;
    }
    gemm_kernel<<<gemmGrid, 256>>>(H, W_dec, b_dec, out, Oo, Dm, 0);
}

// round 3
// speedup vs baseline: 1.1043x; 1.1043x over previous
#include <cuda_runtime.h>
#include <cuda_bf16.h>
#include <math.h>
#include <stdint.h>

// ---------------- problem constants ----------------
#define NL   2
#define Dm   512
#define Nst  16
#define Bb   4
#define Ls   2048
#define Oo   512
#define ML   (Bb*Ls)      // 8192 rows
#define NCH  32           // chunks along L
#define LCH  (Ls/NCH)     // 64

// ---------------- scratch (device globals; no malloc allowed) ----------------
__device__ float g_dt   [ML*Dm];
__device__ float g_bc   [ML*2*Nst];
__device__ float g_y    [ML*Dm];
__device__ float g_mix  [ML*Dm];
__device__ float g_h    [ML*Dm];
__device__ float g_aprod[Bb*NCH*Dm*Nst];
__device__ float g_hend [Bb*NCH*Dm*Nst];
__device__ float g_hstrt[Bb*NCH*Dm*Nst];

// ---------------- helpers ----------------
__device__ __forceinline__ float softplus_f(float v) {
    return fmaxf(v, 0.f) + log1pf(__expf(-fabsf(v)));
}
__device__ __forceinline__ float gelu_f(float v) {
    return 0.5f * v * (1.f + erff(v * 0.70710678118654752f));
}
__device__ __forceinline__ uint32_t smem_u32(const void* p) {
    uint32_t a;
    asm("{ .reg .u64 t; cvta.to.shared.u64 t, %1; cvt.u32.u64 %0, t; }"
        : "=r"(a) : "l"(p));
    return a;
}

// m16n8k16 bf16 mma, fp32 accumulate
__device__ __forceinline__ void mma_bf16(float* d, const uint32_t* a,
                                         uint32_t b0, uint32_t b1) {
    asm volatile(
        "mma.sync.aligned.m16n8k16.row.col.f32.bf16.bf16.f32 "
        "{%0,%1,%2,%3}, {%4,%5,%6,%7}, {%8,%9}, {%0,%1,%2,%3};"
        : "+f"(d[0]), "+f"(d[1]), "+f"(d[2]), "+f"(d[3])
        : "r"(a[0]), "r"(a[1]), "r"(a[2]), "r"(a[3]), "r"(b0), "r"(b1));
}
__device__ __forceinline__ void ldsm_x4(uint32_t* r, uint32_t addr) {
    asm volatile("ldmatrix.sync.aligned.m8n8.x4.shared.b16 {%0,%1,%2,%3}, [%4];"
                 : "=r"(r[0]), "=r"(r[1]), "=r"(r[2]), "=r"(r[3]) : "r"(addr));
}
__device__ __forceinline__ void ldsm_x4_t(uint32_t* r, uint32_t addr) {
    asm volatile("ldmatrix.sync.aligned.m8n8.x4.trans.shared.b16 {%0,%1,%2,%3}, [%4];"
                 : "=r"(r[0]), "=r"(r[1]), "=r"(r[2]), "=r"(r[3]) : "r"(addr));
}

// ---------------- tensor-core GEMM (bf16x3 split, ~fp32 accuracy) ----------
// C[8192,N] = A[8192,512] @ W[512,N] + bias (+softplus if act). N = 512.
// CTA tile 128x128, BK=32, 8 warps (4m x 2n), warp tile 32x64.
#define SA_STR 40     // A smem row stride (bf16 elems), conflict-free ldmatrix
#define SB_STR 136    // B smem row stride

__global__ void __launch_bounds__(256, 2) tgemm_kernel(
    const float* __restrict__ A, const float* __restrict__ W,
    const float* __restrict__ bias, float* __restrict__ C,
    int N, int act)
{
    __shared__ __align__(16) __nv_bfloat16 sAh[128 * SA_STR];
    __shared__ __align__(16) __nv_bfloat16 sAl[128 * SA_STR];
    __shared__ __align__(16) __nv_bfloat16 sBh[32 * SB_STR];
    __shared__ __align__(16) __nv_bfloat16 sBl[32 * SB_STR];

    const int tid = threadIdx.x;
    const int wid = tid >> 5, lane = tid & 31;
    const int wm = wid & 3, wn = wid >> 2;          // warp grid 4m x 2n
    const int row0 = blockIdx.y * 128;
    const int col0 = blockIdx.x * 128;

    float acc[2][8][4];
#pragma unroll
    for (int i = 0; i < 2; ++i)
#pragma unroll
        for (int j = 0; j < 8; ++j)
#pragma unroll
            for (int q = 0; q < 4; ++q) acc[i][j][q] = 0.f;

    // per-thread ldmatrix base offsets (bytes)
    const uint32_t sAh_b = smem_u32(sAh), sAl_b = smem_u32(sAl);
    const uint32_t sBh_b = smem_u32(sBh), sBl_b = smem_u32(sBl);
    const int lr  = lane & 15;            // row within 16
    const int lkc = (lane >> 4) << 3;     // 0 or 8 (k-half select)
    const uint32_t aoff = (uint32_t)(((wm * 32 + lr) * SA_STR + lkc) * 2);
    const uint32_t boff = (uint32_t)((lr * SB_STR + wn * 64 + lkc) * 2);

    for (int kt = 0; kt < 16; ++kt) {
        // ---- load & split A chunk [128 m][32 k]
        {
            const float* Ab = A + (size_t)row0 * Dm + kt * 32;
#pragma unroll
            for (int it = 0; it < 4; ++it) {
                int fid = tid + 256 * it;
                int m = fid >> 3, kf = (fid & 7) << 2;
                float4 v = *(const float4*)(Ab + (size_t)m * Dm + kf);
                __nv_bfloat162 h01 = __float22bfloat162_rn(make_float2(v.x, v.y));
                __nv_bfloat162 h23 = __float22bfloat162_rn(make_float2(v.z, v.w));
                float2 f01 = __bfloat1622float2(h01);
                float2 f23 = __bfloat1622float2(h23);
                __nv_bfloat162 l01 = __float22bfloat162_rn(
                    make_float2(v.x - f01.x, v.y - f01.y));
                __nv_bfloat162 l23 = __float22bfloat162_rn(
                    make_float2(v.z - f23.x, v.w - f23.y));
                uint2 ph, pl;
                ph.x = *(uint32_t*)&h01; ph.y = *(uint32_t*)&h23;
                pl.x = *(uint32_t*)&l01; pl.y = *(uint32_t*)&l23;
                *(uint2*)&sAh[m * SA_STR + kf] = ph;
                *(uint2*)&sAl[m * SA_STR + kf] = pl;
            }
        }
        // ---- load & split B chunk [32 k][128 n] (row-major, n contiguous)
        {
            const float* Wb = W + (size_t)(kt * 32) * N + col0;
#pragma unroll
            for (int it = 0; it < 4; ++it) {
                int fid = tid + 256 * it;
                int k = fid >> 5, nf = (fid & 31) << 2;
                float4 v = *(const float4*)(Wb + (size_t)k * N + nf);
                __nv_bfloat162 h01 = __float22bfloat162_rn(make_float2(v.x, v.y));
                __nv_bfloat162 h23 = __float22bfloat162_rn(make_float2(v.z, v.w));
                float2 f01 = __bfloat1622float2(h01);
                float2 f23 = __bfloat1622float2(h23);
                __nv_bfloat162 l01 = __float22bfloat162_rn(
                    make_float2(v.x - f01.x, v.y - f01.y));
                __nv_bfloat162 l23 = __float22bfloat162_rn(
                    make_float2(v.z - f23.x, v.w - f23.y));
                uint2 ph, pl;
                ph.x = *(uint32_t*)&h01; ph.y = *(uint32_t*)&h23;
                pl.x = *(uint32_t*)&l01; pl.y = *(uint32_t*)&l23;
                *(uint2*)&sBh[k * SB_STR + nf] = ph;
                *(uint2*)&sBl[k * SB_STR + nf] = pl;
            }
        }
        __syncthreads();

        // ---- compute: 2 k16 steps, 3 split terms (hh, hl, lh)
#pragma unroll
        for (int ks = 0; ks < 2; ++ks) {
            uint32_t ah[2][4], al[2][4];
#pragma unroll
            for (int mt = 0; mt < 2; ++mt) {
                uint32_t ao = aoff + (uint32_t)(mt * 16 * SA_STR + ks * 16) * 2;
                ldsm_x4(ah[mt], sAh_b + ao);
                ldsm_x4(al[mt], sAl_b + ao);
            }
#pragma unroll
            for (int nt = 0; nt < 4; ++nt) {
                uint32_t bh[4], bl[4];
                uint32_t bo = boff + (uint32_t)(ks * 16 * SB_STR + nt * 16) * 2;
                ldsm_x4_t(bh, sBh_b + bo);
                ldsm_x4_t(bl, sBl_b + bo);
#pragma unroll
                for (int mt = 0; mt < 2; ++mt) {
                    mma_bf16(acc[mt][nt * 2 + 0], ah[mt], bh[0], bh[1]);
                    mma_bf16(acc[mt][nt * 2 + 0], ah[mt], bl[0], bl[1]);
                    mma_bf16(acc[mt][nt * 2 + 0], al[mt], bh[0], bh[1]);
                    mma_bf16(acc[mt][nt * 2 + 1], ah[mt], bh[2], bh[3]);
                    mma_bf16(acc[mt][nt * 2 + 1], ah[mt], bl[2], bl[3]);
                    mma_bf16(acc[mt][nt * 2 + 1], al[mt], bh[2], bh[3]);
                }
            }
        }
        __syncthreads();
    }

    // ---- epilogue: bias (+softplus), write fp32
#pragma unroll
    for (int mt = 0; mt < 2; ++mt) {
        const int row = row0 + wm * 32 + mt * 16 + (lane >> 2);
#pragma unroll
        for (int nt = 0; nt < 8; ++nt) {
            const int col = col0 + wn * 64 + nt * 8 + ((lane & 3) << 1);
            const float b0 = bias[col], b1 = bias[col + 1];
            float* d = acc[mt][nt];
            float2 o0 = make_float2(d[0] + b0, d[1] + b1);
            float2 o1 = make_float2(d[2] + b0, d[3] + b1);
            if (act) {
                o0.x = softplus_f(o0.x); o0.y = softplus_f(o0.y);
                o1.x = softplus_f(o1.x); o1.y = softplus_f(o1.y);
            }
            *(float2*)(C + (size_t)row * N + col) = o0;
            *(float2*)(C + (size_t)(row + 8) * N + col) = o1;
        }
    }
}

// ---------------- B/C projection: out[row][0:16]=x@W_B+b_B, [16:32]=x@W_C+b_C
__global__ void __launch_bounds__(128) bc_kernel(
    const float* __restrict__ H, const float* __restrict__ WB,
    const float* __restrict__ bB, const float* __restrict__ WC,
    const float* __restrict__ bC, float* __restrict__ outBC)
{
    __shared__ float sW[64][32];
    __shared__ float sX[32][64];
    const int tid = threadIdx.x;
    const int n = tid & 31;
    const int rbase = (tid >> 5) << 3;     // 0,8,16,24
    const int row0 = blockIdx.x * 32;

    float acc[8];
#pragma unroll
    for (int j = 0; j < 8; ++j) acc[j] = 0.f;

    for (int k0 = 0; k0 < Dm; k0 += 64) {
#pragma unroll
        for (int j = 0; j < 2; ++j) {
            int fid = tid + 128 * j;                 // 0..255
            int kk = fid >> 2, nn = (fid & 3) << 2;
            *(float4*)&sW[kk][nn]      = ((const float4*)(WB + k0 * Nst))[fid];
            *(float4*)&sW[kk][nn + 16] = ((const float4*)(WC + k0 * Nst))[fid];
        }
#pragma unroll
        for (int j = 0; j < 4; ++j) {
            int fid = tid + 128 * j;                 // 0..511
            int r = fid >> 4, cc = (fid & 15) << 2;
            *(float4*)&sX[r][cc] = *(const float4*)(H + (row0 + r) * Dm + k0 + cc);
        }
        __syncthreads();
#pragma unroll
        for (int kk = 0; kk < 64; kk += 4) {
            float w0 = sW[kk][n], w1 = sW[kk + 1][n];
            float w2 = sW[kk + 2][n], w3 = sW[kk + 3][n];
#pragma unroll
            for (int j = 0; j < 8; ++j) {
                float4 xv = *(const float4*)&sX[rbase + j][kk];
                acc[j] = fmaf(xv.x, w0, fmaf(xv.y, w1, fmaf(xv.z, w2, fmaf(xv.w, w3, acc[j]))));
            }
        }
        __syncthreads();
    }
    float bias = (n < 16) ? bB[n] : bC[n & 15];
#pragma unroll
    for (int j = 0; j < 8; ++j)
        outBC[(row0 + rbase + j) * 32 + n] = acc[j] + bias;
}

// ---------------- scan pass 1: per-chunk local scan (zero init) ------------
__global__ void __launch_bounds__(128) scan_pass1(
    const float* __restrict__ dtp, const float* __restrict__ Hp,
    const float* __restrict__ Alog, const float* __restrict__ bc,
    float* __restrict__ apo, float* __restrict__ heo)
{
    __shared__ float sBC[LCH][32];
    const int d = blockIdx.x * 128 + threadIdx.x;
    const int c = blockIdx.y, b = blockIdx.z;
    {
        const float4* src = (const float4*)(bc + (b * Ls + c * LCH) * 32);
        float4* dst = (float4*)sBC;
#pragma unroll
        for (int j = 0; j < 4; ++j) dst[threadIdx.x + 128 * j] = src[threadIdx.x + 128 * j];
    }
    __syncthreads();

    float Ac[16];
    {
        const float4* al = (const float4*)(Alog + d * Nst);
#pragma unroll
        for (int q = 0; q < 4; ++q) {
            float4 v = al[q];
            Ac[4 * q + 0] = -expf(v.x); Ac[4 * q + 1] = -expf(v.y);
            Ac[4 * q + 2] = -expf(v.z); Ac[4 * q + 3] = -expf(v.w);
        }
    }
    float h[16], ap[16];
#pragma unroll
    for (int n = 0; n < 16; ++n) { h[n] = 0.f; ap[n] = 1.f; }

    const float* dtr = dtp + (b * Ls + c * LCH) * Dm + d;
    const float* xr  = Hp  + (b * Ls + c * LCH) * Dm + d;
#pragma unroll 2
    for (int t = 0; t < LCH; ++t) {
        float dt = dtr[t * Dm];
        float xv = xr[t * Dm];
        float dtx = dt * xv;
        float bm[16];
        *(float4*)(bm)      = *(const float4*)&sBC[t][0];
        *(float4*)(bm + 4)  = *(const float4*)&sBC[t][4];
        *(float4*)(bm + 8)  = *(const float4*)&sBC[t][8];
        *(float4*)(bm + 12) = *(const float4*)&sBC[t][12];
#pragma unroll
        for (int n = 0; n < 16; ++n) {
            float a = __expf(dt * Ac[n]);
            ap[n] *= a;
            h[n] = fmaf(a, h[n], dtx * bm[n]);
        }
    }
    const int base = ((b * NCH + c) * Dm + d) * Nst;
    float4* po = (float4*)(apo + base);
    float4* ho = (float4*)(heo + base);
#pragma unroll
    for (int q = 0; q < 4; ++q) {
        po[q] = make_float4(ap[4 * q], ap[4 * q + 1], ap[4 * q + 2], ap[4 * q + 3]);
        ho[q] = make_float4(h[4 * q],  h[4 * q + 1],  h[4 * q + 2],  h[4 * q + 3]);
    }
}

// ---------------- scan pass 2: exclusive scan over chunks ------------------
__global__ void __launch_bounds__(256) scan_pass2(
    const float* __restrict__ ap, const float* __restrict__ he,
    float* __restrict__ hs)
{
    const int g = blockIdx.x * 256 + threadIdx.x;   // < Bb*Dm*Nst = 32768
    const int b = g >> 13;
    const int r = g & 8191;
    float carry = 0.f;
#pragma unroll
    for (int c = 0; c < NCH; ++c) {
        const int off = ((b * NCH + c) << 13) + r;
        hs[off] = carry;
        carry = fmaf(ap[off], carry, he[off]);
    }
}

// ---------------- scan pass 3: re-scan with true init + y + GELU -----------
__global__ void __launch_bounds__(128) scan_pass3(
    const float* __restrict__ dtp, const float* __restrict__ Hp,
    const float* __restrict__ Alog, const float* __restrict__ bc,
    const float* __restrict__ hsi, const float* __restrict__ Dsk,
    float* __restrict__ yout)
{
    __shared__ float sBC[LCH][32];
    const int d = blockIdx.x * 128 + threadIdx.x;
    const int c = blockIdx.y, b = blockIdx.z;
    {
        const float4* src = (const float4*)(bc + (b * Ls + c * LCH) * 32);
        float4* dst = (float4*)sBC;
#pragma unroll
        for (int j = 0; j < 4; ++j) dst[threadIdx.x + 128 * j] = src[threadIdx.x + 128 * j];
    }
    __syncthreads();

    float Ac[16];
    {
        const float4* al = (const float4*)(Alog + d * Nst);
#pragma unroll
        for (int q = 0; q < 4; ++q) {
            float4 v = al[q];
            Ac[4 * q + 0] = -expf(v.x); Ac[4 * q + 1] = -expf(v.y);
            Ac[4 * q + 2] = -expf(v.z); Ac[4 * q + 3] = -expf(v.w);
        }
    }
    float h[16];
    {
        const int base = ((b * NCH + c) * Dm + d) * Nst;
        const float4* hi = (const float4*)(hsi + base);
#pragma unroll
        for (int q = 0; q < 4; ++q) {
            float4 v = hi[q];
            h[4 * q] = v.x; h[4 * q + 1] = v.y; h[4 * q + 2] = v.z; h[4 * q + 3] = v.w;
        }
    }
    const float ds = Dsk[d];
    const float* dtr = dtp + (b * Ls + c * LCH) * Dm + d;
    const float* xr  = Hp  + (b * Ls + c * LCH) * Dm + d;
    float* yr = yout + (b * Ls + c * LCH) * Dm + d;

#pragma unroll 2
    for (int t = 0; t < LCH; ++t) {
        float dt = dtr[t * Dm];
        float xv = xr[t * Dm];
        float dtx = dt * xv;
        float bm[16], cm[16];
        *(float4*)(bm)      = *(const float4*)&sBC[t][0];
        *(float4*)(bm + 4)  = *(const float4*)&sBC[t][4];
        *(float4*)(bm + 8)  = *(const float4*)&sBC[t][8];
        *(float4*)(bm + 12) = *(const float4*)&sBC[t][12];
        *(float4*)(cm)      = *(const float4*)&sBC[t][16];
        *(float4*)(cm + 4)  = *(const float4*)&sBC[t][20];
        *(float4*)(cm + 8)  = *(const float4*)&sBC[t][24];
        *(float4*)(cm + 12) = *(const float4*)&sBC[t][28];
        float y0 = 0.f, y1 = 0.f, y2 = 0.f, y3 = 0.f;
#pragma unroll
        for (int n = 0; n < 16; n += 4) {
            float a0 = __expf(dt * Ac[n + 0]);
            float a1 = __expf(dt * Ac[n + 1]);
            float a2 = __expf(dt * Ac[n + 2]);
            float a3 = __expf(dt * Ac[n + 3]);
            h[n + 0] = fmaf(a0, h[n + 0], dtx * bm[n + 0]);
            h[n + 1] = fmaf(a1, h[n + 1], dtx * bm[n + 1]);
            h[n + 2] = fmaf(a2, h[n + 2], dtx * bm[n + 2]);
            h[n + 3] = fmaf(a3, h[n + 3], dtx * bm[n + 3]);
            y0 = fmaf(cm[n + 0], h[n + 0], y0);
            y1 = fmaf(cm[n + 1], h[n + 1], y1);
            y2 = fmaf(cm[n + 2], h[n + 2], y2);
            y3 = fmaf(cm[n + 3], h[n + 3], y3);
        }
        float y = (y0 + y1) + (y2 + y3);
        y = fmaf(ds, xv, y);
        yr[t * Dm] = gelu_f(y);
    }
}

// ---------------- LayerNorm + residual: Out = H + LN(Y)*g + b --------------
__global__ void __launch_bounds__(128) ln_kernel(
    const float* __restrict__ H, const float* __restrict__ Y,
    const float* __restrict__ g, const float* __restrict__ bt,
    float* __restrict__ Out)
{
    __shared__ float red[8];
    const int row = blockIdx.x, tid = threadIdx.x;
    float4 v = ((const float4*)(Y + row * Dm))[tid];
    float s = v.x + v.y + v.z + v.w;
    float q = v.x * v.x + v.y * v.y + v.z * v.z + v.w * v.w;
#pragma unroll
    for (int o = 16; o; o >>= 1) {
        s += __shfl_xor_sync(0xffffffffu, s, o);
        q += __shfl_xor_sync(0xffffffffu, q, o);
    }
    const int w = tid >> 5;
    if ((tid & 31) == 0) { red[w] = s; red[4 + w] = q; }
    __syncthreads();
    s = red[0] + red[1] + red[2] + red[3];
    q = red[4] + red[5] + red[6] + red[7];
    const float mu = s * (1.f / (float)Dm);
    const float var = q * (1.f / (float)Dm) - mu * mu;
    const float inv = rsqrtf(var + 1e-5f);
    float4 gv = ((const float4*)g)[tid];
    float4 bv = ((const float4*)bt)[tid];
    float4 hv = ((const float4*)(H + row * Dm))[tid];
    float4 o;
    o.x = hv.x + (v.x - mu) * inv * gv.x + bv.x;
    o.y = hv.y + (v.y - mu) * inv * gv.y + bv.y;
    o.z = hv.z + (v.z - mu) * inv * gv.z + bv.z;
    o.w = hv.w + (v.w - mu) * inv * gv.w + bv.w;
    ((float4*)(Out + row * Dm))[tid] = o;
}

// ---------------- host launch ----------------
extern "C" void kernel_launch(void* const* d_in, const int* in_sizes, int n_in,
                              void* d_out, int out_size)
{
    const float* x     = (const float*)d_in[0];
    const float* A_log = (const float*)d_in[1];
    const float* W_B   = (const float*)d_in[2];
    const float* b_B   = (const float*)d_in[3];
    const float* W_C   = (const float*)d_in[4];
    const float* b_C   = (const float*)d_in[5];
    const float* W_dt  = (const float*)d_in[6];
    const float* b_dt  = (const float*)d_in[7];
    const float* Dsk   = (const float*)d_in[8];
    const float* W_mix = (const float*)d_in[9];
    const float* b_mix = (const float*)d_in[10];
    const float* ln_g  = (const float*)d_in[11];
    const float* ln_b  = (const float*)d_in[12];
    const float* W_dec = (const float*)d_in[13];
    const float* b_dec = (const float*)d_in[14];
    float* out = (float*)d_out;

    void* p;
    cudaGetSymbolAddress(&p, g_dt);    float* gdt = (float*)p;
    cudaGetSymbolAddress(&p, g_bc);    float* gbc = (float*)p;
    cudaGetSymbolAddress(&p, g_y);     float* gy  = (float*)p;
    cudaGetSymbolAddress(&p, g_mix);   float* gmx = (float*)p;
    cudaGetSymbolAddress(&p, g_h);     float* gh  = (float*)p;
    cudaGetSymbolAddress(&p, g_aprod); float* gap = (float*)p;
    cudaGetSymbolAddress(&p, g_hend);  float* ghe = (float*)p;
    cudaGetSymbolAddress(&p, g_hstrt); float* ghs = (float*)p;

    const dim3 tgGrid(Dm / 128, ML / 128);     // (4, 64)
    const dim3 scanGrid(Dm / 128, NCH, Bb);    // (4, 32, 4)

    const float* H = x;
    for (int i = 0; i < NL; ++i) {
        tgemm_kernel<<<tgGrid, 256>>>(H, W_dt + i * Dm * Dm,
                                      b_dt + i * Dm, gdt, Dm, 1);
        bc_kernel<<<ML / 32, 128>>>(H, W_B + i * Dm * Nst, b_B + i * Nst,
                                    W_C + i * Dm * Nst, b_C + i * Nst, gbc);
        scan_pass1<<<scanGrid, 128>>>(gdt, H, A_log + i * Dm * Nst, gbc, gap, ghe);
        scan_pass2<<<(Bb * Dm * Nst) / 256, 256>>>(gap, ghe, ghs);
        scan_pass3<<<scanGrid, 128>>>(gdt, H, A_log + i * Dm * Nst, gbc, ghs,
                                      Dsk + i * Dm, gy);
        tgemm_kernel<<<tgGrid, 256>>>(gy, W_mix + i * Dm * Dm,
                                      b_mix + i * Dm, gmx, Dm, 0);
        ln_kernel<<<ML, 128>>>(H, gmx, ln_g + i * Dm, ln_b + i * Dm, gh);
        H = gh;
    }
    tgemm_kernel<<<tgGrid, 256>>>(H, W_dec, b_dec, out, Oo, 0);
}

// round 4
// speedup vs baseline: 1.6682x; 1.5106x over previous
#include <cuda_runtime.h>
#include <cuda_bf16.h>
#include <math.h>
#include <stdint.h>

// ---------------- problem constants ----------------
#define NL   2
#define Dm   512
#define Nst  16
#define Bb   4
#define Ls   2048
#define Oo   512
#define ML   (Bb*Ls)      // 8192 rows
#define NCH  32           // chunks along L
#define LCH  (Ls/NCH)     // 64

// ---------------- scratch (device globals; no malloc allowed) ----------------
__device__ float g_dt   [ML*Dm];
__device__ float g_bc   [ML*2*Nst];
__device__ float g_y    [ML*Dm];
__device__ float g_mix  [ML*Dm];
__device__ float g_h    [ML*Dm];
__device__ float g_aprod[Bb*NCH*Dm*Nst];
__device__ float g_hend [Bb*NCH*Dm*Nst];
__device__ float g_hstrt[Bb*NCH*Dm*Nst];
// bf16 split buffers
__device__ __nv_bfloat16 g_ah[ML*Dm];
__device__ __nv_bfloat16 g_al[ML*Dm];
__device__ __nv_bfloat16 g_wh[Dm*Dm];
__device__ __nv_bfloat16 g_wl[Dm*Dm];

// ---------------- helpers ----------------
__device__ __forceinline__ float softplus_f(float v) {
    return fmaxf(v, 0.f) + log1pf(__expf(-fabsf(v)));
}
__device__ __forceinline__ float gelu_f(float v) {
    return 0.5f * v * (1.f + erff(v * 0.70710678118654752f));
}
__device__ __forceinline__ uint32_t smem_u32(const void* p) {
    uint32_t a;
    asm("{ .reg .u64 t; cvta.to.shared.u64 t, %1; cvt.u32.u64 %0, t; }"
        : "=r"(a) : "l"(p));
    return a;
}

// m16n8k16 bf16 mma, fp32 accumulate
__device__ __forceinline__ void mma_bf16(float* d, const uint32_t* a,
                                         uint32_t b0, uint32_t b1) {
    asm volatile(
        "mma.sync.aligned.m16n8k16.row.col.f32.bf16.bf16.f32 "
        "{%0,%1,%2,%3}, {%4,%5,%6,%7}, {%8,%9}, {%0,%1,%2,%3};"
        : "+f"(d[0]), "+f"(d[1]), "+f"(d[2]), "+f"(d[3])
        : "r"(a[0]), "r"(a[1]), "r"(a[2]), "r"(a[3]), "r"(b0), "r"(b1));
}
__device__ __forceinline__ void ldsm_x4(uint32_t* r, uint32_t addr) {
    asm volatile("ldmatrix.sync.aligned.m8n8.x4.shared.b16 {%0,%1,%2,%3}, [%4];"
                 : "=r"(r[0]), "=r"(r[1]), "=r"(r[2]), "=r"(r[3]) : "r"(addr));
}
__device__ __forceinline__ void ldsm_x4_t(uint32_t* r, uint32_t addr) {
    asm volatile("ldmatrix.sync.aligned.m8n8.x4.trans.shared.b16 {%0,%1,%2,%3}, [%4];"
                 : "=r"(r[0]), "=r"(r[1]), "=r"(r[2]), "=r"(r[3]) : "r"(addr));
}
__device__ __forceinline__ void cp16(uint32_t sdst, const void* gsrc) {
    asm volatile("cp.async.cg.shared.global [%0], [%1], 16;"
                 :: "r"(sdst), "l"(gsrc));
}
__device__ __forceinline__ void cp_commit() {
    asm volatile("cp.async.commit_group;");
}
template <int N_>
__device__ __forceinline__ void cp_wait() {
    asm volatile("cp.async.wait_group %0;" :: "n"(N_));
}

// ---------------- split: fp32 -> bf16 hi + bf16 lo (4 elems/thread) --------
__global__ void __launch_bounds__(256) split_kernel(
    const float* __restrict__ src, __nv_bfloat16* __restrict__ hi,
    __nv_bfloat16* __restrict__ lo)
{
    const int i = blockIdx.x * 256 + threadIdx.x;
    float4 v = ((const float4*)src)[i];
    __nv_bfloat162 h01 = __float22bfloat162_rn(make_float2(v.x, v.y));
    __nv_bfloat162 h23 = __float22bfloat162_rn(make_float2(v.z, v.w));
    float2 f01 = __bfloat1622float2(h01);
    float2 f23 = __bfloat1622float2(h23);
    __nv_bfloat162 l01 = __float22bfloat162_rn(make_float2(v.x - f01.x, v.y - f01.y));
    __nv_bfloat162 l23 = __float22bfloat162_rn(make_float2(v.z - f23.x, v.w - f23.y));
    uint2 ph, pl;
    ph.x = *(uint32_t*)&h01; ph.y = *(uint32_t*)&h23;
    pl.x = *(uint32_t*)&l01; pl.y = *(uint32_t*)&l23;
    ((uint2*)hi)[i] = ph;
    ((uint2*)lo)[i] = pl;
}

// ---------------- tensor-core GEMM (bf16x3 split, ~fp32 accuracy) ----------
// C[8192,512] = A[8192,512] @ W[512,512] + bias (+softplus if act)
// CTA tile 128x128, BK=32, 8 warps (4m x 2n), cp.async 2-stage pipeline.
#define SA_STR 40     // A smem row stride (bf16 elems)
#define SB_STR 136    // B smem row stride
#define A_PART 10240  // 128*40*2 bytes
#define B_PART 8704   // 32*136*2 bytes
#define SB_BASE (4*A_PART)                 // 40960
#define SM_SZ  (SB_BASE + 4*B_PART)        // 75776 bytes

__global__ void __launch_bounds__(256, 2) tgemm_kernel(
    const __nv_bfloat16* __restrict__ Ah, const __nv_bfloat16* __restrict__ Al,
    const __nv_bfloat16* __restrict__ Wh, const __nv_bfloat16* __restrict__ Wl,
    const float* __restrict__ bias, float* __restrict__ C, int act)
{
    extern __shared__ char smem[];
    const uint32_t sb = smem_u32(smem);
    const int tid = threadIdx.x;
    const int wid = tid >> 5, lane = tid & 31;
    const int wm = wid & 3, wn = wid >> 2;          // warp grid 4m x 2n
    const int row0 = blockIdx.y * 128;
    const int col0 = blockIdx.x * 128;
    const int N = Dm;

    float acc[2][8][4];
#pragma unroll
    for (int i = 0; i < 2; ++i)
#pragma unroll
        for (int j = 0; j < 8; ++j)
#pragma unroll
            for (int q = 0; q < 4; ++q) acc[i][j][q] = 0.f;

    // per-thread cp.async assignments
    const int am  = tid >> 1;            // A row (2 chunks per row per part)
    const int akc = (tid & 1) << 1;      // chunk 0/1 then +2 handled by i loop? no:
    // A: 512 chunks per part -> each thread does chunks {tid, tid+256}
    // B: 512 chunks per part -> each thread does chunks {tid, tid+256}

    auto issue_stage = [&](int kt, int st) {
        const uint32_t sA = sb + st * 2 * A_PART;
        const uint32_t sB = sb + SB_BASE + st * 2 * B_PART;
#pragma unroll
        for (int i = 0; i < 2; ++i) {
            int ch = tid + 256 * i;
            int m = ch >> 2, kc = ch & 3;
            const size_t go = (size_t)(row0 + m) * Dm + kt * 32 + kc * 8;
            uint32_t so = (uint32_t)(m * SA_STR + kc * 8) * 2;
            cp16(sA + so,          Ah + go);
            cp16(sA + A_PART + so, Al + go);
        }
#pragma unroll
        for (int i = 0; i < 2; ++i) {
            int ch = tid + 256 * i;
            int k = ch >> 4, nc = ch & 15;
            const size_t go = (size_t)(kt * 32 + k) * N + col0 + nc * 8;
            uint32_t so = (uint32_t)(k * SB_STR + nc * 8) * 2;
            cp16(sB + so,          Wh + go);
            cp16(sB + B_PART + so, Wl + go);
        }
        cp_commit();
    };

    // ldmatrix per-thread offsets (bytes, relative to part base)
    const int lr  = lane & 15;
    const int lkc = (lane >> 4) << 3;
    const uint32_t aoff = (uint32_t)(((wm * 32 + lr) * SA_STR + lkc) * 2);
    const uint32_t boff = (uint32_t)((lr * SB_STR + wn * 64 + lkc) * 2);

    issue_stage(0, 0);

    for (int kt = 0; kt < 16; ++kt) {
        if (kt < 15) {
            issue_stage(kt + 1, (kt + 1) & 1);
            cp_wait<1>();
        } else {
            cp_wait<0>();
        }
        __syncthreads();

        const int st = kt & 1;
        const uint32_t sAh_b = sb + st * 2 * A_PART + aoff;
        const uint32_t sAl_b = sAh_b + A_PART;
        const uint32_t sBh_b = sb + SB_BASE + st * 2 * B_PART + boff;
        const uint32_t sBl_b = sBh_b + B_PART;

#pragma unroll
        for (int ks = 0; ks < 2; ++ks) {
            uint32_t ah[2][4], al[2][4];
#pragma unroll
            for (int mt = 0; mt < 2; ++mt) {
                uint32_t ao = (uint32_t)(mt * 16 * SA_STR + ks * 16) * 2;
                ldsm_x4(ah[mt], sAh_b + ao);
                ldsm_x4(al[mt], sAl_b + ao);
            }
#pragma unroll
            for (int nt = 0; nt < 4; ++nt) {
                uint32_t bh[4], bl[4];
                uint32_t bo = (uint32_t)(ks * 16 * SB_STR + nt * 16) * 2;
                ldsm_x4_t(bh, sBh_b + bo);
                ldsm_x4_t(bl, sBl_b + bo);
#pragma unroll
                for (int mt = 0; mt < 2; ++mt) {
                    mma_bf16(acc[mt][nt * 2 + 0], ah[mt], bh[0], bh[1]);
                    mma_bf16(acc[mt][nt * 2 + 0], ah[mt], bl[0], bl[1]);
                    mma_bf16(acc[mt][nt * 2 + 0], al[mt], bh[0], bh[1]);
                    mma_bf16(acc[mt][nt * 2 + 1], ah[mt], bh[2], bh[3]);
                    mma_bf16(acc[mt][nt * 2 + 1], ah[mt], bl[2], bl[3]);
                    mma_bf16(acc[mt][nt * 2 + 1], al[mt], bh[2], bh[3]);
                }
            }
        }
        __syncthreads();
    }

    // ---- epilogue: bias (+softplus), write fp32
#pragma unroll
    for (int mt = 0; mt < 2; ++mt) {
        const int row = row0 + wm * 32 + mt * 16 + (lane >> 2);
#pragma unroll
        for (int nt = 0; nt < 8; ++nt) {
            const int col = col0 + wn * 64 + nt * 8 + ((lane & 3) << 1);
            const float b0 = bias[col], b1 = bias[col + 1];
            float* d = acc[mt][nt];
            float2 o0 = make_float2(d[0] + b0, d[1] + b1);
            float2 o1 = make_float2(d[2] + b0, d[3] + b1);
            if (act) {
                o0.x = softplus_f(o0.x); o0.y = softplus_f(o0.y);
                o1.x = softplus_f(o1.x); o1.y = softplus_f(o1.y);
            }
            *(float2*)(C + (size_t)row * N + col) = o0;
            *(float2*)(C + (size_t)(row + 8) * N + col) = o1;
        }
    }
}

// ---------------- B/C projection: out[row][0:16]=x@W_B+b_B, [16:32]=x@W_C+b_C
__global__ void __launch_bounds__(128) bc_kernel(
    const float* __restrict__ H, const float* __restrict__ WB,
    const float* __restrict__ bB, const float* __restrict__ WC,
    const float* __restrict__ bC, float* __restrict__ outBC)
{
    __shared__ float sW[64][32];
    __shared__ float sX[32][64];
    const int tid = threadIdx.x;
    const int n = tid & 31;
    const int rbase = (tid >> 5) << 3;     // 0,8,16,24
    const int row0 = blockIdx.x * 32;

    float acc[8];
#pragma unroll
    for (int j = 0; j < 8; ++j) acc[j] = 0.f;

    for (int k0 = 0; k0 < Dm; k0 += 64) {
#pragma unroll
        for (int j = 0; j < 2; ++j) {
            int fid = tid + 128 * j;                 // 0..255
            int kk = fid >> 2, nn = (fid & 3) << 2;
            *(float4*)&sW[kk][nn]      = ((const float4*)(WB + k0 * Nst))[fid];
            *(float4*)&sW[kk][nn + 16] = ((const float4*)(WC + k0 * Nst))[fid];
        }
#pragma unroll
        for (int j = 0; j < 4; ++j) {
            int fid = tid + 128 * j;                 // 0..511
            int r = fid >> 4, cc = (fid & 15) << 2;
            *(float4*)&sX[r][cc] = *(const float4*)(H + (row0 + r) * Dm + k0 + cc);
        }
        __syncthreads();
#pragma unroll
        for (int kk = 0; kk < 64; kk += 4) {
            float w0 = sW[kk][n], w1 = sW[kk + 1][n];
            float w2 = sW[kk + 2][n], w3 = sW[kk + 3][n];
#pragma unroll
            for (int j = 0; j < 8; ++j) {
                float4 xv = *(const float4*)&sX[rbase + j][kk];
                acc[j] = fmaf(xv.x, w0, fmaf(xv.y, w1, fmaf(xv.z, w2, fmaf(xv.w, w3, acc[j]))));
            }
        }
        __syncthreads();
    }
    float bias = (n < 16) ? bB[n] : bC[n & 15];
#pragma unroll
    for (int j = 0; j < 8; ++j)
        outBC[(row0 + rbase + j) * 32 + n] = acc[j] + bias;
}

// ---------------- scan pass 1: per-chunk local scan (zero init) ------------
__global__ void __launch_bounds__(128) scan_pass1(
    const float* __restrict__ dtp, const float* __restrict__ Hp,
    const float* __restrict__ Alog, const float* __restrict__ bc,
    float* __restrict__ apo, float* __restrict__ heo)
{
    __shared__ float sBC[LCH][32];
    const int d = blockIdx.x * 128 + threadIdx.x;
    const int c = blockIdx.y, b = blockIdx.z;
    {
        const float4* src = (const float4*)(bc + (b * Ls + c * LCH) * 32);
        float4* dst = (float4*)sBC;
#pragma unroll
        for (int j = 0; j < 4; ++j) dst[threadIdx.x + 128 * j] = src[threadIdx.x + 128 * j];
    }
    __syncthreads();

    float Ac[16];
    {
        const float4* al = (const float4*)(Alog + d * Nst);
#pragma unroll
        for (int q = 0; q < 4; ++q) {
            float4 v = al[q];
            Ac[4 * q + 0] = -expf(v.x); Ac[4 * q + 1] = -expf(v.y);
            Ac[4 * q + 2] = -expf(v.z); Ac[4 * q + 3] = -expf(v.w);
        }
    }
    float h[16], ap[16];
#pragma unroll
    for (int n = 0; n < 16; ++n) { h[n] = 0.f; ap[n] = 1.f; }

    const float* dtr = dtp + (b * Ls + c * LCH) * Dm + d;
    const float* xr  = Hp  + (b * Ls + c * LCH) * Dm + d;
#pragma unroll 2
    for (int t = 0; t < LCH; ++t) {
        float dt = dtr[t * Dm];
        float xv = xr[t * Dm];
        float dtx = dt * xv;
        float bm[16];
        *(float4*)(bm)      = *(const float4*)&sBC[t][0];
        *(float4*)(bm + 4)  = *(const float4*)&sBC[t][4];
        *(float4*)(bm + 8)  = *(const float4*)&sBC[t][8];
        *(float4*)(bm + 12) = *(const float4*)&sBC[t][12];
#pragma unroll
        for (int n = 0; n < 16; ++n) {
            float a = __expf(dt * Ac[n]);
            ap[n] *= a;
            h[n] = fmaf(a, h[n], dtx * bm[n]);
        }
    }
    const int base = ((b * NCH + c) * Dm + d) * Nst;
    float4* po = (float4*)(apo + base);
    float4* ho = (float4*)(heo + base);
#pragma unroll
    for (int q = 0; q < 4; ++q) {
        po[q] = make_float4(ap[4 * q], ap[4 * q + 1], ap[4 * q + 2], ap[4 * q + 3]);
        ho[q] = make_float4(h[4 * q],  h[4 * q + 1],  h[4 * q + 2],  h[4 * q + 3]);
    }
}

// ---------------- scan pass 2: exclusive scan over chunks ------------------
__global__ void __launch_bounds__(256) scan_pass2(
    const float* __restrict__ ap, const float* __restrict__ he,
    float* __restrict__ hs)
{
    const int g = blockIdx.x * 256 + threadIdx.x;   // < Bb*Dm*Nst = 32768
    const int b = g >> 13;
    const int r = g & 8191;
    float carry = 0.f;
#pragma unroll
    for (int c = 0; c < NCH; ++c) {
        const int off = ((b * NCH + c) << 13) + r;
        hs[off] = carry;
        carry = fmaf(ap[off], carry, he[off]);
    }
}

// ---------------- scan pass 3: re-scan with true init + y + GELU -----------
__global__ void __launch_bounds__(128) scan_pass3(
    const float* __restrict__ dtp, const float* __restrict__ Hp,
    const float* __restrict__ Alog, const float* __restrict__ bc,
    const float* __restrict__ hsi, const float* __restrict__ Dsk,
    float* __restrict__ yout)
{
    __shared__ float sBC[LCH][32];
    const int d = blockIdx.x * 128 + threadIdx.x;
    const int c = blockIdx.y, b = blockIdx.z;
    {
        const float4* src = (const float4*)(bc + (b * Ls + c * LCH) * 32);
        float4* dst = (float4*)sBC;
#pragma unroll
        for (int j = 0; j < 4; ++j) dst[threadIdx.x + 128 * j] = src[threadIdx.x + 128 * j];
    }
    __syncthreads();

    float Ac[16];
    {
        const float4* al = (const float4*)(Alog + d * Nst);
#pragma unroll
        for (int q = 0; q < 4; ++q) {
            float4 v = al[q];
            Ac[4 * q + 0] = -expf(v.x); Ac[4 * q + 1] = -expf(v.y);
            Ac[4 * q + 2] = -expf(v.z); Ac[4 * q + 3] = -expf(v.w);
        }
    }
    float h[16];
    {
        const int base = ((b * NCH + c) * Dm + d) * Nst;
        const float4* hi = (const float4*)(hsi + base);
#pragma unroll
        for (int q = 0; q < 4; ++q) {
            float4 v = hi[q];
            h[4 * q] = v.x; h[4 * q + 1] = v.y; h[4 * q + 2] = v.z; h[4 * q + 3] = v.w;
        }
    }
    const float ds = Dsk[d];
    const float* dtr = dtp + (b * Ls + c * LCH) * Dm + d;
    const float* xr  = Hp  + (b * Ls + c * LCH) * Dm + d;
    float* yr = yout + (b * Ls + c * LCH) * Dm + d;

#pragma unroll 2
    for (int t = 0; t < LCH; ++t) {
        float dt = dtr[t * Dm];
        float xv = xr[t * Dm];
        float dtx = dt * xv;
        float bm[16], cm[16];
        *(float4*)(bm)      = *(const float4*)&sBC[t][0];
        *(float4*)(bm + 4)  = *(const float4*)&sBC[t][4];
        *(float4*)(bm + 8)  = *(const float4*)&sBC[t][8];
        *(float4*)(bm + 12) = *(const float4*)&sBC[t][12];
        *(float4*)(cm)      = *(const float4*)&sBC[t][16];
        *(float4*)(cm + 4)  = *(const float4*)&sBC[t][20];
        *(float4*)(cm + 8)  = *(const float4*)&sBC[t][24];
        *(float4*)(cm + 12) = *(const float4*)&sBC[t][28];
        float y0 = 0.f, y1 = 0.f, y2 = 0.f, y3 = 0.f;
#pragma unroll
        for (int n = 0; n < 16; n += 4) {
            float a0 = __expf(dt * Ac[n + 0]);
            float a1 = __expf(dt * Ac[n + 1]);
            float a2 = __expf(dt * Ac[n + 2]);
            float a3 = __expf(dt * Ac[n + 3]);
            h[n + 0] = fmaf(a0, h[n + 0], dtx * bm[n + 0]);
            h[n + 1] = fmaf(a1, h[n + 1], dtx * bm[n + 1]);
            h[n + 2] = fmaf(a2, h[n + 2], dtx * bm[n + 2]);
            h[n + 3] = fmaf(a3, h[n + 3], dtx * bm[n + 3]);
            y0 = fmaf(cm[n + 0], h[n + 0], y0);
            y1 = fmaf(cm[n + 1], h[n + 1], y1);
            y2 = fmaf(cm[n + 2], h[n + 2], y2);
            y3 = fmaf(cm[n + 3], h[n + 3], y3);
        }
        float y = (y0 + y1) + (y2 + y3);
        y = fmaf(ds, xv, y);
        yr[t * Dm] = gelu_f(y);
    }
}

// ---------------- LayerNorm + residual: Out = H + LN(Y)*g + b --------------
__global__ void __launch_bounds__(128) ln_kernel(
    const float* __restrict__ H, const float* __restrict__ Y,
    const float* __restrict__ g, const float* __restrict__ bt,
    float* __restrict__ Out)
{
    __shared__ float red[8];
    const int row = blockIdx.x, tid = threadIdx.x;
    float4 v = ((const float4*)(Y + row * Dm))[tid];
    float s = v.x + v.y + v.z + v.w;
    float q = v.x * v.x + v.y * v.y + v.z * v.z + v.w * v.w;
#pragma unroll
    for (int o = 16; o; o >>= 1) {
        s += __shfl_xor_sync(0xffffffffu, s, o);
        q += __shfl_xor_sync(0xffffffffu, q, o);
    }
    const int w = tid >> 5;
    if ((tid & 31) == 0) { red[w] = s; red[4 + w] = q; }
    __syncthreads();
    s = red[0] + red[1] + red[2] + red[3];
    q = red[4] + red[5] + red[6] + red[7];
    const float mu = s * (1.f / (float)Dm);
    const float var = q * (1.f / (float)Dm) - mu * mu;
    const float inv = rsqrtf(var + 1e-5f);
    float4 gv = ((const float4*)g)[tid];
    float4 bv = ((const float4*)bt)[tid];
    float4 hv = ((const float4*)(H + row * Dm))[tid];
    float4 o;
    o.x = hv.x + (v.x - mu) * inv * gv.x + bv.x;
    o.y = hv.y + (v.y - mu) * inv * gv.y + bv.y;
    o.z = hv.z + (v.z - mu) * inv * gv.z + bv.z;
    o.w = hv.w + (v.w - mu) * inv * gv.w + bv.w;
    ((float4*)(Out + row * Dm))[tid] = o;
}

// ---------------- host launch ----------------
extern "C" void kernel_launch(void* const* d_in, const int* in_sizes, int n_in,
                              void* d_out, int out_size)
{
    const float* x     = (const float*)d_in[0];
    const float* A_log = (const float*)d_in[1];
    const float* W_B   = (const float*)d_in[2];
    const float* b_B   = (const float*)d_in[3];
    const float* W_C   = (const float*)d_in[4];
    const float* b_C   = (const float*)d_in[5];
    const float* W_dt  = (const float*)d_in[6];
    const float* b_dt  = (const float*)d_in[7];
    const float* Dsk   = (const float*)d_in[8];
    const float* W_mix = (const float*)d_in[9];
    const float* b_mix = (const float*)d_in[10];
    const float* ln_g  = (const float*)d_in[11];
    const float* ln_b  = (const float*)d_in[12];
    const float* W_dec = (const float*)d_in[13];
    const float* b_dec = (const float*)d_in[14];
    float* out = (float*)d_out;

    void* p;
    cudaGetSymbolAddress(&p, g_dt);    float* gdt = (float*)p;
    cudaGetSymbolAddress(&p, g_bc);    float* gbc = (float*)p;
    cudaGetSymbolAddress(&p, g_y);     float* gy  = (float*)p;
    cudaGetSymbolAddress(&p, g_mix);   float* gmx = (float*)p;
    cudaGetSymbolAddress(&p, g_h);     float* gh  = (float*)p;
    cudaGetSymbolAddress(&p, g_aprod); float* gap = (float*)p;
    cudaGetSymbolAddress(&p, g_hend);  float* ghe = (float*)p;
    cudaGetSymbolAddress(&p, g_hstrt); float* ghs = (float*)p;
    cudaGetSymbolAddress(&p, g_ah);    __nv_bfloat16* gah = (__nv_bfloat16*)p;
    cudaGetSymbolAddress(&p, g_al);    __nv_bfloat16* gal = (__nv_bfloat16*)p;
    cudaGetSymbolAddress(&p, g_wh);    __nv_bfloat16* gwh = (__nv_bfloat16*)p;
    cudaGetSymbolAddress(&p, g_wl);    __nv_bfloat16* gwl = (__nv_bfloat16*)p;

    static bool attr_done = false;
    if (!attr_done) {
        cudaFuncSetAttribute(tgemm_kernel,
                             cudaFuncAttributeMaxDynamicSharedMemorySize, SM_SZ);
        attr_done = true;
    }

    const dim3 tgGrid(Dm / 128, ML / 128);     // (4, 64)
    const dim3 scanGrid(Dm / 128, NCH, Bb);    // (4, 32, 4)
    const int splitA_blocks = (ML * Dm / 4) / 256;   // 4096
    const int splitW_blocks = (Dm * Dm / 4) / 256;   // 256

    auto do_gemm = [&](const float* Aq, const float* Wq, const float* bq,
                       float* Cq, int act) {
        split_kernel<<<splitA_blocks, 256>>>(Aq, gah, gal);
        split_kernel<<<splitW_blocks, 256>>>(Wq, gwh, gwl);
        tgemm_kernel<<<tgGrid, 256, SM_SZ>>>(gah, gal, gwh, gwl, bq, Cq, act);
    };

    const float* H = x;
    for (int i = 0; i < NL; ++i) {
        do_gemm(H, W_dt + i * Dm * Dm, b_dt + i * Dm, gdt, 1);
        bc_kernel<<<ML / 32, 128>>>(H, W_B + i * Dm * Nst, b_B + i * Nst,
                                    W_C + i * Dm * Nst, b_C + i * Nst, gbc);
        scan_pass1<<<scanGrid, 128>>>(gdt, H, A_log + i * Dm * Nst, gbc, gap, ghe);
        scan_pass2<<<(Bb * Dm * Nst) / 256, 256>>>(gap, ghe, ghs);
        scan_pass3<<<scanGrid, 128>>>(gdt, H, A_log + i * Dm * Nst, gbc, ghs,
                                      Dsk + i * Dm, gy);
        do_gemm(gy, W_mix + i * Dm * Dm, b_mix + i * Dm, gmx, 0);
        ln_kernel<<<ML, 128>>>(H, gmx, ln_g + i * Dm, ln_b + i * Dm, gh);
        H = gh;
    }
    do_gemm(H, W_dec, b_dec, out, 0);
}